// round 3
// baseline (speedup 1.0000x reference)
#include <cuda_runtime.h>
#include <cuda_bf16.h>

// Problem constants (fixed by the reference)
#define BB 2
#define CC 64
#define HH 512
#define WW 512
#define HW (HH * WW)          // 262144
#define NN 4096
#define KK 5
#define NPAIR (BB * NN)       // 8192
#define INV_MAXDIST (1.0f / 724.07733f)
#define FEAT_THRESH_NOMATCH 16.0f
#define FINAL_SCALE (1.0f / ((KK + 1.0f) * NN))   // 1/24576

// Scratch (allocation-free rule: __device__ globals)
__device__ float g_fr[NPAIR * CC];     // compacted ref features   [b][i][c]
__device__ float g_fo[NPAIR * CC];     // compacted other features [b][i][c]
__device__ float g_partial[NPAIR];     // per-match loss partial

// ---------------------------------------------------------------------------
// Kernel A: fused gather of BOTH tensors. One thread per (b,i,q), q in [0,16),
// owning channels 4q..4q+3 of both fr and fo. 8 independent strided LDGs
// (front-batched -> MLP=8), two coalesced float4 stores.
// ---------------------------------------------------------------------------
__global__ void __launch_bounds__(256) gather_both_kernel(
        const float* __restrict__ ref,
        const float* __restrict__ oth,
        const int* __restrict__ inds_ref,
        const int* __restrict__ inds_other) {
    int tid = blockIdx.x * blockDim.x + threadIdx.x;   // 0 .. NPAIR*16-1
    if (tid >= NPAIR * 16) return;
    int q  = tid & 15;
    int bi = tid >> 4;            // b*N + i
    int b  = bi >> 12;
    int i  = bi & (NN - 1);

    int xr = __ldg(&inds_ref  [b * 2 * NN + i]);
    int yr = __ldg(&inds_ref  [b * 2 * NN + NN + i]);
    int xo = __ldg(&inds_other[b * 2 * NN + i]);
    int yo = __ldg(&inds_other[b * 2 * NN + NN + i]);
    size_t linr = (size_t)(HH * yr + xr);
    size_t lino = (size_t)(HH * yo + xo);

    const float* rp = ref + (size_t)(b * CC + 4 * q) * HW + linr;
    const float* op = oth + (size_t)(b * CC + 4 * q) * HW + lino;

    // 8 independent gathers — front-batched (MLP ~ 8)
    float r0 = __ldg(rp + 0 * HW);
    float o0 = __ldg(op + 0 * HW);
    float r1 = __ldg(rp + 1 * HW);
    float o1 = __ldg(op + 1 * HW);
    float r2 = __ldg(rp + 2 * HW);
    float o2 = __ldg(op + 2 * HW);
    float r3 = __ldg(rp + 3 * HW);
    float o3 = __ldg(op + 3 * HW);

    reinterpret_cast<float4*>(g_fr)[tid] = make_float4(r0, r1, r2, r3);
    reinterpret_cast<float4*>(g_fo)[tid] = make_float4(o0, o1, o2, o3);
}

// ---------------------------------------------------------------------------
// Kernel B: one warp per match pair; all feature reads are coalesced from the
// compacted arrays (L2-resident, ~4 MB total).
// ---------------------------------------------------------------------------
__global__ void __launch_bounds__(256) match_kernel(
        const float* __restrict__ weights,
        const int* __restrict__ inds_ref,
        const int* __restrict__ rand_inds) {
    int gwarp = (blockIdx.x * blockDim.x + threadIdx.x) >> 5;
    int lane  = threadIdx.x & 31;
    if (gwarp >= NPAIR) return;
    int b = gwarp >> 12;
    int i = gwarp & (NN - 1);

    const float2* frp = reinterpret_cast<const float2*>(g_fr + (size_t)gwarp * CC);
    const float2* fop = reinterpret_cast<const float2*>(g_fo + (size_t)gwarp * CC);
    float2 fr = frp[lane];
    float2 fo = fop[lane];
    float d0 = fr.x - fo.x, d1 = fr.y - fo.y;
    float sm = d0 * d0 + d1 * d1;

    int   jarr[KK];
    float sk[KK];
    const int* ri = rand_inds + (size_t)gwarp * KK;
#pragma unroll
    for (int k = 0; k < KK; k++) {
        int j = __ldg(ri + k);             // uniform across the warp (broadcast)
        jarr[k] = j;
        const float2* fo_j =
            reinterpret_cast<const float2*>(g_fo + (size_t)(b * NN + j) * CC);
        float2 fj = fo_j[lane];
        float e0 = fr.x - fj.x, e1 = fr.y - fj.y;
        sk[k] = e0 * e0 + e1 * e1;
    }

    // warp reduction of 6 sums
#pragma unroll
    for (int off = 16; off > 0; off >>= 1) {
        sm += __shfl_down_sync(0xFFFFFFFFu, sm, off);
#pragma unroll
        for (int k = 0; k < KK; k++)
            sk[k] += __shfl_down_sync(0xFFFFFFFFu, sk[k], off);
    }

    if (lane == 0) {
        int xr = inds_ref[b * 2 * NN + i];
        int yr = inds_ref[b * 2 * NN + NN + i];
        float total = weights[b * NN + i] * fmaxf(sm, 0.0f);
#pragma unroll
        for (int k = 0; k < KK; k++) {
            int j  = jarr[k];
            float xj = (float)inds_ref[b * 2 * NN + j];
            float yj = (float)inds_ref[b * 2 * NN + NN + j];
            float dx = (float)xr - xj;
            float dy = (float)yr - yj;
            float dist = sqrtf(dx * dx + dy * dy);
            total += (-dist * INV_MAXDIST) * fminf(sk[k], FEAT_THRESH_NOMATCH);
        }
        g_partial[gwarp] = total * FINAL_SCALE;
    }
}

// ---------------------------------------------------------------------------
// Kernel C: deterministic single-block reduction of the 8192 partials.
// ---------------------------------------------------------------------------
__global__ void reduce_kernel(float* __restrict__ out) {
    __shared__ float s[256];
    float acc = 0.0f;
    for (int idx = threadIdx.x; idx < NPAIR; idx += 256)
        acc += g_partial[idx];
    s[threadIdx.x] = acc;
    __syncthreads();
#pragma unroll
    for (int stride = 128; stride > 0; stride >>= 1) {
        if (threadIdx.x < stride) s[threadIdx.x] += s[threadIdx.x + stride];
        __syncthreads();
    }
    if (threadIdx.x == 0) out[0] = s[0];
}

extern "C" void kernel_launch(void* const* d_in, const int* in_sizes, int n_in,
                              void* d_out, int out_size) {
    const float* inputs_ref   = (const float*)d_in[0];
    const float* inputs_other = (const float*)d_in[1];
    const float* weights      = (const float*)d_in[2];
    const int*   inds_ref     = (const int*)d_in[3];
    const int*   inds_other   = (const int*)d_in[4];
    const int*   rand_inds    = (const int*)d_in[5];
    float* out = (float*)d_out;

    // A: NPAIR*16 threads, 8 gathers each
    gather_both_kernel<<<(NPAIR * 16 + 255) / 256, 256>>>(
        inputs_ref, inputs_other, inds_ref, inds_other);
    // B: one warp per pair
    match_kernel<<<(NPAIR * 32 + 255) / 256, 256>>>(weights, inds_ref, rand_inds);
    // C: single block, deterministic
    reduce_kernel<<<1, 256>>>(out);
}